// round 13
// baseline (speedup 1.0000x reference)
#include <cuda_runtime.h>
#include <cuda_bf16.h>

#define NKER 25
#define HP   8        // padded inner dim (6 feats + basis-sum + pad)
#define HROW 200      // NKER * HP floats per node
#define HW   150      // logical 25*6
#define JD   156      // 150 + 6 (H rows + x rows)
#define CD   78       // 75 Z cols + 3 root cols
#define NG   26       // float4 col-groups (3 real cols each)
#define NGP  27       // padded row stride in float4 (bank stagger)
#define GH   13       // groups per half
#define NMAX 50000
#define EMAX 1600000

// scratch (no cudaMalloc allowed)
__device__ float  g_H[NMAX * HROW];     // 40 MB
__device__ float  g_inv[NMAX];
__device__ float4 g_X8[NMAX * 2];       // x packed 32B-aligned: {x0..x5,0,0}
__device__ float4 g_Z4[NMAX * NKER];    // 20 MB, (z0,z1,z2,pad) per (n,kk)
__device__ float4 g_ZE[NMAX * 64];      // 51 MB: [n][16 bases][4 corners]
__device__ float4 g_A4[NMAX];           // edge-2 accumulator
__device__ float  g_M[JD * CD];         // fused weight matrix

// ---------------------------------------------------------------------------
__global__ void k_zero(const float* __restrict__ x, int N) {
    int i = blockIdx.x * blockDim.x + threadIdx.x;
    int stride = gridDim.x * blockDim.x;
    float4 z4 = make_float4(0.f, 0.f, 0.f, 0.f);
    float4* H4 = reinterpret_cast<float4*>(g_H);
    int nH4 = N * (HROW / 4);
    for (int t = i; t < nH4; t += stride) H4[t] = z4;
    for (int t = i; t < N; t += stride) {
        g_A4[t] = z4;
        const float2* x2 = reinterpret_cast<const float2*>(x) + t * 3;
        float2 xa = x2[0], xb = x2[1], xc = x2[2];
        g_X8[2 * t]     = make_float4(xa.x, xa.y, xb.x, xb.y);
        g_X8[2 * t + 1] = make_float4(xc.x, xc.y, 0.f, 0.f);
    }
}

// degree-1 open B-spline, K=5: 4 corners
__device__ __forceinline__ void spline4(float p0, float p1, float* b, int* id) {
    float v0 = p0 * 4.0f, v1 = p1 * 4.0f;
    float fl0 = floorf(v0), fl1 = floorf(v1);
    int i0 = (int)fl0, i1 = (int)fl1;
    i0 = min(max(i0, 0), 3);
    i1 = min(max(i1, 0), 3);
    float f0 = v0 - fl0, f1 = v1 - fl1;
    float g0 = 1.0f - f0, g1 = 1.0f - f1;
    b[0] = g0 * g1; b[1] = f0 * g1; b[2] = g0 * f1; b[3] = f0 * f1;
    int base = i0 + 5 * i1;
    id[0] = base; id[1] = base + 1; id[2] = base + 5; id[3] = base + 6;
}

// same but returns the 4x4 base index (i0 + 4*i1) for the ZE table
__device__ __forceinline__ int spline4_base(float p0, float p1, float* b) {
    float v0 = p0 * 4.0f, v1 = p1 * 4.0f;
    float fl0 = floorf(v0), fl1 = floorf(v1);
    int i0 = (int)fl0, i1 = (int)fl1;
    i0 = min(max(i0, 0), 3);
    i1 = min(max(i1, 0), 3);
    float f0 = v0 - fl0, f1 = v1 - fl1;
    float g0 = 1.0f - f0, g1 = 1.0f - f1;
    b[0] = g0 * g1; b[1] = f0 * g1; b[2] = g0 * f1; b[3] = f0 * f1;
    return i0 + 4 * i1;
}

// ---------------------------------------------------------------------------
// Edge pass 1: H[dst, idx_s, 0:6] += basis_s * x[src, :]; slot6 += basis_s
__global__ void k_edge1(const int* __restrict__ ei, const float* __restrict__ ps,
                        int E) {
    int e = blockIdx.x * blockDim.x + threadIdx.x;
    if (e >= E) return;
    int dst = ei[e];
    int src = ei[E + e];
    float2 p = reinterpret_cast<const float2*>(ps)[e];
    float b[4]; int id[4];
    spline4(p.x, p.y, b, id);
    float4 xa = __ldg(g_X8 + 2 * src);
    float4 xb = __ldg(g_X8 + 2 * src + 1);
    float4* Hd = reinterpret_cast<float4*>(g_H + (size_t)dst * HROW);
#pragma unroll
    for (int s = 0; s < 4; s++) {
        float bs = b[s];
        float4* hp = Hd + id[s] * 2;
        atomicAdd(hp,     make_float4(bs * xa.x, bs * xa.y, bs * xa.z, bs * xa.w));
        atomicAdd(hp + 1, make_float4(bs * xb.x, bs * xb.y, bs, 0.f));
    }
}

// ---------------------------------------------------------------------------
// Build fused M (156 x 78). Block j; 4 i-slices per col, smem reduce.
__global__ void k_buildM(const float* __restrict__ w, const float* __restrict__ rw,
                         const float* __restrict__ w1, const float* __restrict__ rw1) {
    __shared__ float sA[1024];
    __shared__ float red[CD][4];
    int j = blockIdx.x;
    int tid = threadIdx.x;
    const float* Arow = (j < HW) ? (w + (j / 6) * 6144 + (j % 6) * 1024)
                                 : (rw + (j - HW) * 1024);
    for (int i = tid; i < 1024; i += blockDim.x) sA[i] = Arow[i];
    __syncthreads();
    int c = tid >> 2, sl = tid & 3;
    if (c < CD) {
        const float* Bp = (c < 75) ? (w1 + (c / 3) * 3072 + (c % 3)) : (rw1 + (c - 75));
        float acc = 0.f;
        int i0 = sl * 256;
#pragma unroll 8
        for (int i = i0; i < i0 + 256; i++) acc = fmaf(sA[i], __ldg(Bp + i * 3), acc);
        red[c][sl] = acc;
    }
    __syncthreads();
    if (tid < CD)
        g_M[j * CD + tid] = (red[tid][0] + red[tid][1]) + (red[tid][2] + red[tid][3]);
}

// ---------------------------------------------------------------------------
// Z GEMM: 2 nodes per thread x 39-col half. Per j: 13 LDS.128 -> 78 FMA. (R9 version)
__global__ void __launch_bounds__(128, 3)
k_zgemm(float* __restrict__ dout, int N) {
    extern __shared__ float4 sB4[];   // [JD][NGP] = 156*27*16 = 67392 B
    int tid = threadIdx.x;
    int n0 = blockIdx.x * 128;

    for (int idx = tid; idx < JD * NG; idx += 128) {
        int j = idx / NG, g = idx - j * NG;
        const float* m = g_M + j * CD + 3 * g;
        sB4[j * NGP + g] = make_float4(m[0], m[1], m[2], 0.f);
    }
    __syncthreads();

    int half = tid >> 6;          // 0 or 1
    int r    = tid & 63;          // node-pair index
    int na = n0 + 2 * r;
    int nb = na + 1;
    bool va = (na < N), vb = (nb < N);

    const float4* sB = sB4 + half * GH;   // this half's column base

    float accA[GH][3], accB[GH][3];
#pragma unroll
    for (int g = 0; g < GH; g++) {
        accA[g][0] = accA[g][1] = accA[g][2] = 0.f;
        accB[g][0] = accB[g][1] = accB[g][2] = 0.f;
    }

    const float4* HA = reinterpret_cast<const float4*>(g_H + (size_t)na * HROW);
    const float4* HB = reinterpret_cast<const float4*>(g_H + (size_t)nb * HROW);
    float dA = 0.f, dB = 0.f;
    const float4 z4 = make_float4(0.f, 0.f, 0.f, 0.f);

    for (int k = 0; k < NKER; k++) {
        float4 ha0 = va ? __ldg(HA + 2 * k)     : z4;
        float4 ha1 = va ? __ldg(HA + 2 * k + 1) : z4;
        float4 hb0 = vb ? __ldg(HB + 2 * k)     : z4;
        float4 hb1 = vb ? __ldg(HB + 2 * k + 1) : z4;
        dA += ha1.z; dB += hb1.z;
        float avA[6] = {ha0.x, ha0.y, ha0.z, ha0.w, ha1.x, ha1.y};
        float avB[6] = {hb0.x, hb0.y, hb0.z, hb0.w, hb1.x, hb1.y};
#pragma unroll
        for (int i = 0; i < 6; i++) {
            float aA = avA[i], aB = avB[i];
            const float4* mrow = sB + (k * 6 + i) * NGP;
#pragma unroll
            for (int g = 0; g < GH; g++) {
                float4 b = mrow[g];
                accA[g][0] = fmaf(aA, b.x, accA[g][0]);
                accA[g][1] = fmaf(aA, b.y, accA[g][1]);
                accA[g][2] = fmaf(aA, b.z, accA[g][2]);
                accB[g][0] = fmaf(aB, b.x, accB[g][0]);
                accB[g][1] = fmaf(aB, b.y, accB[g][1]);
                accB[g][2] = fmaf(aB, b.z, accB[g][2]);
            }
        }
    }

    float invA = 1.0f / fmaxf(dA, 1.0f);
    float invB = 1.0f / fmaxf(dB, 1.0f);
    if (half == 0) {
        if (va) g_inv[na] = invA;
        if (vb) g_inv[nb] = invB;
    }
#pragma unroll
    for (int g = 0; g < GH; g++) {
        accA[g][0] *= invA; accA[g][1] *= invA; accA[g][2] *= invA;
        accB[g][0] *= invB; accB[g][1] *= invB; accB[g][2] *= invB;
    }

    // x part (rows 150..155 of M), unscaled — both halves, own columns
    float4 xaA = va ? __ldg(g_X8 + 2 * na)     : z4;
    float4 xbA = va ? __ldg(g_X8 + 2 * na + 1) : z4;
    float4 xaB = vb ? __ldg(g_X8 + 2 * nb)     : z4;
    float4 xbB = vb ? __ldg(g_X8 + 2 * nb + 1) : z4;
    float xvA[6] = {xaA.x, xaA.y, xaA.z, xaA.w, xbA.x, xbA.y};
    float xvB[6] = {xaB.x, xaB.y, xaB.z, xaB.w, xbB.x, xbB.y};
#pragma unroll
    for (int i = 0; i < 6; i++) {
        float aA = xvA[i], aB = xvB[i];
        const float4* mrow = sB + (HW + i) * NGP;
#pragma unroll
        for (int g = 0; g < GH; g++) {
            float4 b = mrow[g];
            accA[g][0] = fmaf(aA, b.x, accA[g][0]);
            accA[g][1] = fmaf(aA, b.y, accA[g][1]);
            accA[g][2] = fmaf(aA, b.z, accA[g][2]);
            accB[g][0] = fmaf(aB, b.x, accB[g][0]);
            accB[g][1] = fmaf(aB, b.y, accB[g][1]);
            accB[g][2] = fmaf(aB, b.z, accB[g][2]);
        }
    }

    // stores: half0 -> kk 0..12 ; half1 -> kk 13..24 + root cols
    if (half == 0) {
        if (va) {
            float4* Zn = g_Z4 + (size_t)na * NKER;
#pragma unroll
            for (int g = 0; g < GH; g++)
                Zn[g] = make_float4(accA[g][0], accA[g][1], accA[g][2], 0.f);
        }
        if (vb) {
            float4* Zn = g_Z4 + (size_t)nb * NKER;
#pragma unroll
            for (int g = 0; g < GH; g++)
                Zn[g] = make_float4(accB[g][0], accB[g][1], accB[g][2], 0.f);
        }
    } else {
        if (va) {
            float4* Zn = g_Z4 + (size_t)na * NKER;
#pragma unroll
            for (int g = 0; g < GH - 1; g++)
                Zn[13 + g] = make_float4(accA[g][0], accA[g][1], accA[g][2], 0.f);
            dout[na * 3 + 0] = accA[GH - 1][0];
            dout[na * 3 + 1] = accA[GH - 1][1];
            dout[na * 3 + 2] = accA[GH - 1][2];
        }
        if (vb) {
            float4* Zn = g_Z4 + (size_t)nb * NKER;
#pragma unroll
            for (int g = 0; g < GH - 1; g++)
                Zn[13 + g] = make_float4(accB[g][0], accB[g][1], accB[g][2], 0.f);
            dout[nb * 3 + 0] = accB[GH - 1][0];
            dout[nb * 3 + 1] = accB[GH - 1][1];
            dout[nb * 3 + 2] = accB[GH - 1][2];
        }
    }
}

// ---------------------------------------------------------------------------
// Expand Z into per-base corner sets: ZE[n][b=i0+4*i1] = {Z[k],Z[k+1],Z[k+5],Z[k+6]}
// One thread per (node, base): 4 coalesced-ish reads (L2-hot), one 64B write.
__global__ void k_expand(int N) {
    int t = blockIdx.x * blockDim.x + threadIdx.x;
    int n = t >> 4;
    if (n >= N) return;
    int b = t & 15;
    int i0 = b & 3, i1 = b >> 2;
    int k = i0 + 5 * i1;
    const float4* Zn = g_Z4 + (size_t)n * NKER;
    float4* out = g_ZE + ((size_t)n * 16 + b) * 4;
    out[0] = __ldg(Zn + k);
    out[1] = __ldg(Zn + k + 1);
    out[2] = __ldg(Zn + k + 5);
    out[3] = __ldg(Zn + k + 6);
}

// ---------------------------------------------------------------------------
// Edge pass 2: one 64B contiguous corner-set read per edge, one float4 atomic.
__global__ void k_edge2(const int* __restrict__ ei, const float* __restrict__ ps,
                        int E) {
    int e = blockIdx.x * blockDim.x + threadIdx.x;
    if (e >= E) return;
    int dst = ei[e];
    int src = ei[E + e];
    float2 p = reinterpret_cast<const float2*>(ps)[e];
    float b[4];
    int base = spline4_base(p.x, p.y, b);
    const float4* Zp = g_ZE + ((size_t)src * 16 + base) * 4;
    float4 z0 = __ldg(Zp);
    float4 z1 = __ldg(Zp + 1);
    float4 z2 = __ldg(Zp + 2);
    float4 z3 = __ldg(Zp + 3);
    float a0 = b[0] * z0.x + b[1] * z1.x + b[2] * z2.x + b[3] * z3.x;
    float a1 = b[0] * z0.y + b[1] * z1.y + b[2] * z2.y + b[3] * z3.y;
    float a2 = b[0] * z0.z + b[1] * z1.z + b[2] * z2.z + b[3] * z3.z;
    atomicAdd(g_A4 + dst, make_float4(a0, a1, a2, 0.f));
}

// ---------------------------------------------------------------------------
// Final: out[n] = root_term (already in dout) + inv[n] * A4[n]
__global__ void k_final(float* __restrict__ dout, int N) {
    int n = blockIdx.x * blockDim.x + threadIdx.x;
    if (n >= N) return;
    float4 a = g_A4[n];
    float inv = g_inv[n];
    dout[n * 3 + 0] += a.x * inv;
    dout[n * 3 + 1] += a.y * inv;
    dout[n * 3 + 2] += a.z * inv;
}

// ---------------------------------------------------------------------------
extern "C" void kernel_launch(void* const* d_in, const int* in_sizes, int n_in,
                              void* d_out, int out_size) {
    const float* x   = (const float*)d_in[0];
    const int*   ei  = (const int*)d_in[1];
    const float* ps  = (const float*)d_in[2];
    const float* ps1 = (const float*)d_in[3];
    const float* w   = (const float*)d_in[4];
    const float* rw  = (const float*)d_in[5];
    const float* w1  = (const float*)d_in[6];
    const float* rw1 = (const float*)d_in[7];
    float* dout = (float*)d_out;

    int N = in_sizes[0] / 6;
    int E = in_sizes[2] / 2;
    if (N > NMAX) N = NMAX;
    if (E > EMAX) E = EMAX;

    k_zero<<<2048, 256>>>(x, N);
    k_edge1<<<(E + 255) / 256, 256>>>(ei, ps, E);
    k_buildM<<<JD, 320>>>(w, rw, w1, rw1);

    size_t smemC = (size_t)(JD * NGP) * sizeof(float4);   // 67392 B
    cudaFuncSetAttribute(k_zgemm, cudaFuncAttributeMaxDynamicSharedMemorySize, (int)smemC);
    k_zgemm<<<(N + 127) / 128, 128, smemC>>>(dout, N);

    k_expand<<<(N * 16 + 255) / 256, 256>>>(N);
    k_edge2<<<(E + 255) / 256, 256>>>(ei, ps1, E);
    k_final<<<(N + 255) / 256, 256>>>(dout, N);
}

// round 15
// speedup vs baseline: 1.1253x; 1.1253x over previous
#include <cuda_runtime.h>
#include <cuda_bf16.h>

#define NKER 25
#define HP   8        // padded inner dim (6 feats + basis-sum + pad)
#define HROW 200      // NKER * HP floats per node
#define HW   150      // logical 25*6
#define JD   156      // 150 + 6 (H rows + x rows)
#define CD   78       // 75 Z cols + 3 root cols
#define SMP  84       // smem row pitch in floats (2 halves x 40 + 4 pad)
#define NMAX 50000
#define EMAX 1600000

// scratch (no cudaMalloc allowed)
__device__ float  g_H[NMAX * HROW];     // 40 MB
__device__ float  g_inv[NMAX];
__device__ float4 g_X8[NMAX * 2];       // x packed 32B-aligned: {x0..x5,0,0}
__device__ float4 g_Z4[NMAX * NKER];    // 20 MB, (z0,z1,z2,pad) per (n,kk)
__device__ float4 g_A4[NMAX];           // edge-2 accumulator
__device__ float  g_M[JD * CD];         // fused weight matrix

// ---- packed f32x2 helpers ---------------------------------------------------
__device__ __forceinline__ unsigned long long pack2(float lo, float hi) {
    unsigned long long r;
    asm("mov.b64 %0, {%1, %2};" : "=l"(r) : "f"(lo), "f"(hi));
    return r;
}
__device__ __forceinline__ void unpack2(unsigned long long v, float& lo, float& hi) {
    asm("mov.b64 {%0, %1}, %2;" : "=f"(lo), "=f"(hi) : "l"(v));
}
#define FFMA2(acc, a2, b2) \
    asm("fma.rn.f32x2 %0, %1, %2, %0;" : "+l"(acc) : "l"(a2), "l"(b2))
__device__ __forceinline__ unsigned long long mul2(unsigned long long a,
                                                   unsigned long long b) {
    unsigned long long d;
    asm("mul.rn.f32x2 %0, %1, %2;" : "=l"(d) : "l"(a), "l"(b));
    return d;
}

// ---------------------------------------------------------------------------
__global__ void k_zero(const float* __restrict__ x, int N) {
    int i = blockIdx.x * blockDim.x + threadIdx.x;
    int stride = gridDim.x * blockDim.x;
    float4 z4 = make_float4(0.f, 0.f, 0.f, 0.f);
    float4* H4 = reinterpret_cast<float4*>(g_H);
    int nH4 = N * (HROW / 4);
    for (int t = i; t < nH4; t += stride) H4[t] = z4;
    for (int t = i; t < N; t += stride) {
        g_A4[t] = z4;
        const float2* x2 = reinterpret_cast<const float2*>(x) + t * 3;
        float2 xa = x2[0], xb = x2[1], xc = x2[2];
        g_X8[2 * t]     = make_float4(xa.x, xa.y, xb.x, xb.y);
        g_X8[2 * t + 1] = make_float4(xc.x, xc.y, 0.f, 0.f);
    }
}

// degree-1 open B-spline, K=5: 4 corners
__device__ __forceinline__ void spline4(float p0, float p1, float* b, int* id) {
    float v0 = p0 * 4.0f, v1 = p1 * 4.0f;
    float fl0 = floorf(v0), fl1 = floorf(v1);
    int i0 = (int)fl0, i1 = (int)fl1;
    i0 = min(max(i0, 0), 3);
    i1 = min(max(i1, 0), 3);
    float f0 = v0 - fl0, f1 = v1 - fl1;
    float g0 = 1.0f - f0, g1 = 1.0f - f1;
    b[0] = g0 * g1; b[1] = f0 * g1; b[2] = g0 * f1; b[3] = f0 * f1;
    int base = i0 + 5 * i1;
    id[0] = base; id[1] = base + 1; id[2] = base + 5; id[3] = base + 6;
}

// ---------------------------------------------------------------------------
// Edge pass 1: H[dst, idx_s, 0:6] += basis_s * x[src, :]; slot6 += basis_s
__global__ void k_edge1(const int* __restrict__ ei, const float* __restrict__ ps,
                        int E) {
    int e = blockIdx.x * blockDim.x + threadIdx.x;
    if (e >= E) return;
    int dst = ei[e];
    int src = ei[E + e];
    float2 p = reinterpret_cast<const float2*>(ps)[e];
    float b[4]; int id[4];
    spline4(p.x, p.y, b, id);
    float4 xa = __ldg(g_X8 + 2 * src);
    float4 xb = __ldg(g_X8 + 2 * src + 1);
    float4* Hd = reinterpret_cast<float4*>(g_H + (size_t)dst * HROW);
#pragma unroll
    for (int s = 0; s < 4; s++) {
        float bs = b[s];
        float4* hp = Hd + id[s] * 2;
        atomicAdd(hp,     make_float4(bs * xa.x, bs * xa.y, bs * xa.z, bs * xa.w));
        atomicAdd(hp + 1, make_float4(bs * xb.x, bs * xb.y, bs, 0.f));
    }
}

// ---------------------------------------------------------------------------
// Build fused M (156 x 78). Block j; 4 i-slices per col, smem reduce.
__global__ void k_buildM(const float* __restrict__ w, const float* __restrict__ rw,
                         const float* __restrict__ w1, const float* __restrict__ rw1) {
    __shared__ float sA[1024];
    __shared__ float red[CD][4];
    int j = blockIdx.x;
    int tid = threadIdx.x;
    const float* Arow = (j < HW) ? (w + (j / 6) * 6144 + (j % 6) * 1024)
                                 : (rw + (j - HW) * 1024);
    for (int i = tid; i < 1024; i += blockDim.x) sA[i] = Arow[i];
    __syncthreads();
    int c = tid >> 2, sl = tid & 3;
    if (c < CD) {
        const float* Bp = (c < 75) ? (w1 + (c / 3) * 3072 + (c % 3)) : (rw1 + (c - 75));
        float acc = 0.f;
        int i0 = sl * 256;
#pragma unroll 8
        for (int i = i0; i < i0 + 256; i++) acc = fmaf(sA[i], __ldg(Bp + i * 3), acc);
        red[c][sl] = acc;
    }
    __syncthreads();
    if (tid < CD)
        g_M[j * CD + tid] = (red[tid][0] + red[tid][1]) + (red[tid][2] + red[tid][3]);
}

// ---------------------------------------------------------------------------
// Z GEMM with packed f32x2 FMA: 2 nodes/thread x 39-col half.
// smem row j: [half0: 39 cols + pad][half1: 39 cols + pad], contiguous pairs.
// Per j-row: 10 LDS.128 (as double2) + 2 packs + 40 FFMA2.
__global__ void __launch_bounds__(128, 3)
k_zgemm(float* __restrict__ dout, int N) {
    extern __shared__ float sB[];   // JD*SMP = 156*84*4 = 52416 B (dynamic)
    int tid = threadIdx.x;
    int n0 = blockIdx.x * 128;

    for (int idx = tid; idx < JD * 80; idx += 128) {
        int j = idx / 80, t = idx - j * 80;
        int hf = t / 40, lc = t - hf * 40;
        sB[j * SMP + t] = (lc < 39) ? g_M[j * CD + hf * 39 + lc] : 0.f;
    }
    __syncthreads();

    int half = tid >> 6;          // 0 or 1
    int r    = tid & 63;          // node-pair index
    int na = n0 + 2 * r;
    int nb = na + 1;
    bool va = (na < N), vb = (nb < N);
    int hoff = half * 40;

    unsigned long long accA[20], accB[20];
#pragma unroll
    for (int p = 0; p < 20; p++) { accA[p] = 0ull; accB[p] = 0ull; }

    const float4* HA = reinterpret_cast<const float4*>(g_H + (size_t)na * HROW);
    const float4* HB = reinterpret_cast<const float4*>(g_H + (size_t)nb * HROW);
    float dA = 0.f, dB = 0.f;
    const float4 z4 = make_float4(0.f, 0.f, 0.f, 0.f);

    for (int k = 0; k < NKER; k++) {
        float4 ha0 = va ? __ldg(HA + 2 * k)     : z4;
        float4 ha1 = va ? __ldg(HA + 2 * k + 1) : z4;
        float4 hb0 = vb ? __ldg(HB + 2 * k)     : z4;
        float4 hb1 = vb ? __ldg(HB + 2 * k + 1) : z4;
        dA += ha1.z; dB += hb1.z;
        float avA[6] = {ha0.x, ha0.y, ha0.z, ha0.w, ha1.x, ha1.y};
        float avB[6] = {hb0.x, hb0.y, hb0.z, hb0.w, hb1.x, hb1.y};
#pragma unroll
        for (int i = 0; i < 6; i++) {
            const double2* row = reinterpret_cast<const double2*>(
                sB + (k * 6 + i) * SMP + hoff);
            unsigned long long aA2 = pack2(avA[i], avA[i]);
            unsigned long long aB2 = pack2(avB[i], avB[i]);
#pragma unroll
            for (int p = 0; p < 10; p++) {
                double2 bb = row[p];
                unsigned long long b0 = __double_as_longlong(bb.x);
                unsigned long long b1 = __double_as_longlong(bb.y);
                FFMA2(accA[2 * p],     aA2, b0);
                FFMA2(accA[2 * p + 1], aA2, b1);
                FFMA2(accB[2 * p],     aB2, b0);
                FFMA2(accB[2 * p + 1], aB2, b1);
            }
        }
    }

    float invA = 1.0f / fmaxf(dA, 1.0f);
    float invB = 1.0f / fmaxf(dB, 1.0f);
    if (half == 0) {
        if (va) g_inv[na] = invA;
        if (vb) g_inv[nb] = invB;
    }
    unsigned long long iA2 = pack2(invA, invA);
    unsigned long long iB2 = pack2(invB, invB);
#pragma unroll
    for (int p = 0; p < 20; p++) {
        accA[p] = mul2(accA[p], iA2);
        accB[p] = mul2(accB[p], iB2);
    }

    // x part (rows 150..155 of M), unscaled
    float4 xaA = va ? __ldg(g_X8 + 2 * na)     : z4;
    float4 xbA = va ? __ldg(g_X8 + 2 * na + 1) : z4;
    float4 xaB = vb ? __ldg(g_X8 + 2 * nb)     : z4;
    float4 xbB = vb ? __ldg(g_X8 + 2 * nb + 1) : z4;
    float xvA[6] = {xaA.x, xaA.y, xaA.z, xaA.w, xbA.x, xbA.y};
    float xvB[6] = {xaB.x, xaB.y, xaB.z, xaB.w, xbB.x, xbB.y};
#pragma unroll
    for (int i = 0; i < 6; i++) {
        const double2* row = reinterpret_cast<const double2*>(
            sB + (HW + i) * SMP + hoff);
        unsigned long long aA2 = pack2(xvA[i], xvA[i]);
        unsigned long long aB2 = pack2(xvB[i], xvB[i]);
#pragma unroll
        for (int p = 0; p < 10; p++) {
            double2 bb = row[p];
            unsigned long long b0 = __double_as_longlong(bb.x);
            unsigned long long b1 = __double_as_longlong(bb.y);
            FFMA2(accA[2 * p],     aA2, b0);
            FFMA2(accA[2 * p + 1], aA2, b1);
            FFMA2(accB[2 * p],     aB2, b0);
            FFMA2(accB[2 * p + 1], aB2, b1);
        }
    }

    float fA[40], fB[40];
#pragma unroll
    for (int p = 0; p < 20; p++) {
        unpack2(accA[p], fA[2 * p], fA[2 * p + 1]);
        unpack2(accB[p], fB[2 * p], fB[2 * p + 1]);
    }

    // stores: half0 -> kk 0..12 ; half1 -> kk 13..24 + root cols (local 36..38)
    if (half == 0) {
        if (va) {
            float4* Zn = g_Z4 + (size_t)na * NKER;
#pragma unroll
            for (int g = 0; g < 13; g++)
                Zn[g] = make_float4(fA[3 * g], fA[3 * g + 1], fA[3 * g + 2], 0.f);
        }
        if (vb) {
            float4* Zn = g_Z4 + (size_t)nb * NKER;
#pragma unroll
            for (int g = 0; g < 13; g++)
                Zn[g] = make_float4(fB[3 * g], fB[3 * g + 1], fB[3 * g + 2], 0.f);
        }
    } else {
        if (va) {
            float4* Zn = g_Z4 + (size_t)na * NKER;
#pragma unroll
            for (int g = 0; g < 12; g++)
                Zn[13 + g] = make_float4(fA[3 * g], fA[3 * g + 1], fA[3 * g + 2], 0.f);
            dout[na * 3 + 0] = fA[36];
            dout[na * 3 + 1] = fA[37];
            dout[na * 3 + 2] = fA[38];
        }
        if (vb) {
            float4* Zn = g_Z4 + (size_t)nb * NKER;
#pragma unroll
            for (int g = 0; g < 12; g++)
                Zn[13 + g] = make_float4(fB[3 * g], fB[3 * g + 1], fB[3 * g + 2], 0.f);
            dout[nb * 3 + 0] = fB[36];
            dout[nb * 3 + 1] = fB[37];
            dout[nb * 3 + 2] = fB[38];
        }
    }
}

// ---------------------------------------------------------------------------
// Edge pass 2: A4[dst] += sum_s basis1_s * Z[src, idx_s, :]  (one float4 atomic)
__global__ void k_edge2(const int* __restrict__ ei, const float* __restrict__ ps,
                        int E) {
    int e = blockIdx.x * blockDim.x + threadIdx.x;
    if (e >= E) return;
    int dst = ei[e];
    int src = ei[E + e];
    float2 p = reinterpret_cast<const float2*>(ps)[e];
    float b[4]; int id[4];
    spline4(p.x, p.y, b, id);
    const float4* Z = g_Z4 + (size_t)src * NKER;
    float a0 = 0.f, a1 = 0.f, a2 = 0.f;
#pragma unroll
    for (int s = 0; s < 4; s++) {
        float4 z = __ldg(Z + id[s]);
        a0 = fmaf(b[s], z.x, a0);
        a1 = fmaf(b[s], z.y, a1);
        a2 = fmaf(b[s], z.z, a2);
    }
    atomicAdd(g_A4 + dst, make_float4(a0, a1, a2, 0.f));
}

// ---------------------------------------------------------------------------
// Final: out[n] = root_term (already in dout) + inv[n] * A4[n]
__global__ void k_final(float* __restrict__ dout, int N) {
    int n = blockIdx.x * blockDim.x + threadIdx.x;
    if (n >= N) return;
    float4 a = g_A4[n];
    float inv = g_inv[n];
    dout[n * 3 + 0] += a.x * inv;
    dout[n * 3 + 1] += a.y * inv;
    dout[n * 3 + 2] += a.z * inv;
}

// ---------------------------------------------------------------------------
extern "C" void kernel_launch(void* const* d_in, const int* in_sizes, int n_in,
                              void* d_out, int out_size) {
    const float* x   = (const float*)d_in[0];
    const int*   ei  = (const int*)d_in[1];
    const float* ps  = (const float*)d_in[2];
    const float* ps1 = (const float*)d_in[3];
    const float* w   = (const float*)d_in[4];
    const float* rw  = (const float*)d_in[5];
    const float* w1  = (const float*)d_in[6];
    const float* rw1 = (const float*)d_in[7];
    float* dout = (float*)d_out;

    int N = in_sizes[0] / 6;
    int E = in_sizes[2] / 2;
    if (N > NMAX) N = NMAX;
    if (E > EMAX) E = EMAX;

    k_zero<<<2048, 256>>>(x, N);
    k_edge1<<<(E + 255) / 256, 256>>>(ei, ps, E);
    k_buildM<<<JD, 320>>>(w, rw, w1, rw1);

    size_t smemC = (size_t)(JD * SMP) * sizeof(float);   // 52416 B
    cudaFuncSetAttribute(k_zgemm, cudaFuncAttributeMaxDynamicSharedMemorySize, (int)smemC);
    k_zgemm<<<(N + 127) / 128, 128, smemC>>>(dout, N);

    k_edge2<<<(E + 255) / 256, 256>>>(ei, ps1, E);
    k_final<<<(N + 255) / 256, 256>>>(dout, N);
}

// round 16
// speedup vs baseline: 1.3066x; 1.1611x over previous
#include <cuda_runtime.h>
#include <cuda_bf16.h>

#define NKER 25
#define HP   8        // padded inner dim (6 feats + basis-sum + pad)
#define HROW 200      // NKER * HP floats per node
#define HW   150      // logical 25*6
#define JD   156      // 150 + 6 (H rows + x rows)
#define CD   78       // 75 Z cols + 3 root cols
#define SMP  84       // smem row pitch in floats (2 halves x 40 + 4 pad)
#define NMAX 50000
#define EMAX 1600000

// scratch (no cudaMalloc allowed)
__device__ float  g_H[NMAX * HROW];     // 40 MB
__device__ float  g_inv[NMAX];
__device__ float4 g_X8[NMAX * 2];       // x packed 32B-aligned: {x0..x5,0,0}
__device__ float4 g_Z4[NMAX * NKER];    // 20 MB, (z0,z1,z2,pad) per (n,kk)
__device__ float4 g_A4[NMAX];           // edge-2 accumulator
__device__ float  g_M[JD * CD];         // fused weight matrix

// ---- packed f32x2 helpers ---------------------------------------------------
__device__ __forceinline__ unsigned long long pack2(float lo, float hi) {
    unsigned long long r;
    asm("mov.b64 %0, {%1, %2};" : "=l"(r) : "f"(lo), "f"(hi));
    return r;
}
__device__ __forceinline__ void unpack2(unsigned long long v, float& lo, float& hi) {
    asm("mov.b64 {%0, %1}, %2;" : "=f"(lo), "=f"(hi) : "l"(v));
}
#define FFMA2(acc, a2, b2) \
    asm("fma.rn.f32x2 %0, %1, %2, %0;" : "+l"(acc) : "l"(a2), "l"(b2))
__device__ __forceinline__ unsigned long long mul2(unsigned long long a,
                                                   unsigned long long b) {
    unsigned long long d;
    asm("mul.rn.f32x2 %0, %1, %2;" : "=l"(d) : "l"(a), "l"(b));
    return d;
}

// ---------------------------------------------------------------------------
__global__ void k_zero(const float* __restrict__ x, int N) {
    int i = blockIdx.x * blockDim.x + threadIdx.x;
    int stride = gridDim.x * blockDim.x;
    float4 z4 = make_float4(0.f, 0.f, 0.f, 0.f);
    float4* H4 = reinterpret_cast<float4*>(g_H);
    int nH4 = N * (HROW / 4);
    for (int t = i; t < nH4; t += stride) H4[t] = z4;
    for (int t = i; t < N; t += stride) {
        g_A4[t] = z4;
        const float2* x2 = reinterpret_cast<const float2*>(x) + t * 3;
        float2 xa = x2[0], xb = x2[1], xc = x2[2];
        g_X8[2 * t]     = make_float4(xa.x, xa.y, xb.x, xb.y);
        g_X8[2 * t + 1] = make_float4(xc.x, xc.y, 0.f, 0.f);
    }
}

// degree-1 open B-spline, K=5: 4 corners
__device__ __forceinline__ void spline4(float p0, float p1, float* b, int* id) {
    float v0 = p0 * 4.0f, v1 = p1 * 4.0f;
    float fl0 = floorf(v0), fl1 = floorf(v1);
    int i0 = (int)fl0, i1 = (int)fl1;
    i0 = min(max(i0, 0), 3);
    i1 = min(max(i1, 0), 3);
    float f0 = v0 - fl0, f1 = v1 - fl1;
    float g0 = 1.0f - f0, g1 = 1.0f - f1;
    b[0] = g0 * g1; b[1] = f0 * g1; b[2] = g0 * f1; b[3] = f0 * f1;
    int base = i0 + 5 * i1;
    id[0] = base; id[1] = base + 1; id[2] = base + 5; id[3] = base + 6;
}

// ---------------------------------------------------------------------------
// Fused edge1 + buildM: blocks [0, JD) build M; blocks [JD, ...) do edge pass 1.
// Independent outputs (g_M vs g_H); co-scheduling hides buildM's L2 streaming
// under edge1's atomic-issue-bound time.
__global__ void __launch_bounds__(256)
k_edge1_buildM(const int* __restrict__ ei, const float* __restrict__ ps, int E,
               const float* __restrict__ w, const float* __restrict__ rw,
               const float* __restrict__ w1, const float* __restrict__ rw1) {
    __shared__ float sA[1024];
    __shared__ float red[CD][2];
    int tid = threadIdx.x;

    if (blockIdx.x < JD) {
        // ---- buildM role: M[j, :] = Arow(1024) @ Wc(1024 x 78) ----
        int j = blockIdx.x;
        const float* Arow = (j < HW) ? (w + (j / 6) * 6144 + (j % 6) * 1024)
                                     : (rw + (j - HW) * 1024);
        for (int i = tid; i < 1024; i += 256) sA[i] = Arow[i];
        __syncthreads();
        int c = tid >> 1, sl = tid & 1;
        if (c < CD) {
            const float* Bp = (c < 75) ? (w1 + (c / 3) * 3072 + (c % 3))
                                       : (rw1 + (c - 75));
            float acc = 0.f;
            int i0 = sl * 512;
#pragma unroll 8
            for (int i = i0; i < i0 + 512; i++)
                acc = fmaf(sA[i], __ldg(Bp + i * 3), acc);
            red[c][sl] = acc;
        }
        __syncthreads();
        if (tid < CD)
            g_M[j * CD + tid] = red[tid][0] + red[tid][1];
        return;
    }

    // ---- edge1 role ----
    int e = (blockIdx.x - JD) * 256 + tid;
    if (e >= E) return;
    int dst = ei[e];
    int src = ei[E + e];
    float2 p = reinterpret_cast<const float2*>(ps)[e];
    float b[4]; int id[4];
    spline4(p.x, p.y, b, id);
    float4 xa = __ldg(g_X8 + 2 * src);
    float4 xb = __ldg(g_X8 + 2 * src + 1);
    float4* Hd = reinterpret_cast<float4*>(g_H + (size_t)dst * HROW);
#pragma unroll
    for (int s = 0; s < 4; s++) {
        float bs = b[s];
        float4* hp = Hd + id[s] * 2;
        atomicAdd(hp,     make_float4(bs * xa.x, bs * xa.y, bs * xa.z, bs * xa.w));
        atomicAdd(hp + 1, make_float4(bs * xb.x, bs * xb.y, bs, 0.f));
    }
}

// ---------------------------------------------------------------------------
// Z GEMM with packed f32x2 FMA: 2 nodes/thread x 39-col half. (R15 winner)
__global__ void __launch_bounds__(128, 3)
k_zgemm(float* __restrict__ dout, int N) {
    extern __shared__ float sB[];   // JD*SMP = 52416 B (dynamic)
    int tid = threadIdx.x;
    int n0 = blockIdx.x * 128;

    for (int idx = tid; idx < JD * 80; idx += 128) {
        int j = idx / 80, t = idx - j * 80;
        int hf = t / 40, lc = t - hf * 40;
        sB[j * SMP + t] = (lc < 39) ? g_M[j * CD + hf * 39 + lc] : 0.f;
    }
    __syncthreads();

    int half = tid >> 6;          // 0 or 1
    int r    = tid & 63;          // node-pair index
    int na = n0 + 2 * r;
    int nb = na + 1;
    bool va = (na < N), vb = (nb < N);
    int hoff = half * 40;

    unsigned long long accA[20], accB[20];
#pragma unroll
    for (int p = 0; p < 20; p++) { accA[p] = 0ull; accB[p] = 0ull; }

    const float4* HA = reinterpret_cast<const float4*>(g_H + (size_t)na * HROW);
    const float4* HB = reinterpret_cast<const float4*>(g_H + (size_t)nb * HROW);
    float dA = 0.f, dB = 0.f;
    const float4 z4 = make_float4(0.f, 0.f, 0.f, 0.f);

    for (int k = 0; k < NKER; k++) {
        float4 ha0 = va ? __ldg(HA + 2 * k)     : z4;
        float4 ha1 = va ? __ldg(HA + 2 * k + 1) : z4;
        float4 hb0 = vb ? __ldg(HB + 2 * k)     : z4;
        float4 hb1 = vb ? __ldg(HB + 2 * k + 1) : z4;
        dA += ha1.z; dB += hb1.z;
        float avA[6] = {ha0.x, ha0.y, ha0.z, ha0.w, ha1.x, ha1.y};
        float avB[6] = {hb0.x, hb0.y, hb0.z, hb0.w, hb1.x, hb1.y};
#pragma unroll
        for (int i = 0; i < 6; i++) {
            const double2* row = reinterpret_cast<const double2*>(
                sB + (k * 6 + i) * SMP + hoff);
            unsigned long long aA2 = pack2(avA[i], avA[i]);
            unsigned long long aB2 = pack2(avB[i], avB[i]);
#pragma unroll
            for (int p = 0; p < 10; p++) {
                double2 bb = row[p];
                unsigned long long b0 = __double_as_longlong(bb.x);
                unsigned long long b1 = __double_as_longlong(bb.y);
                FFMA2(accA[2 * p],     aA2, b0);
                FFMA2(accA[2 * p + 1], aA2, b1);
                FFMA2(accB[2 * p],     aB2, b0);
                FFMA2(accB[2 * p + 1], aB2, b1);
            }
        }
    }

    float invA = 1.0f / fmaxf(dA, 1.0f);
    float invB = 1.0f / fmaxf(dB, 1.0f);
    if (half == 0) {
        if (va) g_inv[na] = invA;
        if (vb) g_inv[nb] = invB;
    }
    unsigned long long iA2 = pack2(invA, invA);
    unsigned long long iB2 = pack2(invB, invB);
#pragma unroll
    for (int p = 0; p < 20; p++) {
        accA[p] = mul2(accA[p], iA2);
        accB[p] = mul2(accB[p], iB2);
    }

    // x part (rows 150..155 of M), unscaled
    float4 xaA = va ? __ldg(g_X8 + 2 * na)     : z4;
    float4 xbA = va ? __ldg(g_X8 + 2 * na + 1) : z4;
    float4 xaB = vb ? __ldg(g_X8 + 2 * nb)     : z4;
    float4 xbB = vb ? __ldg(g_X8 + 2 * nb + 1) : z4;
    float xvA[6] = {xaA.x, xaA.y, xaA.z, xaA.w, xbA.x, xbA.y};
    float xvB[6] = {xaB.x, xaB.y, xaB.z, xaB.w, xbB.x, xbB.y};
#pragma unroll
    for (int i = 0; i < 6; i++) {
        const double2* row = reinterpret_cast<const double2*>(
            sB + (HW + i) * SMP + hoff);
        unsigned long long aA2 = pack2(xvA[i], xvA[i]);
        unsigned long long aB2 = pack2(xvB[i], xvB[i]);
#pragma unroll
        for (int p = 0; p < 10; p++) {
            double2 bb = row[p];
            unsigned long long b0 = __double_as_longlong(bb.x);
            unsigned long long b1 = __double_as_longlong(bb.y);
            FFMA2(accA[2 * p],     aA2, b0);
            FFMA2(accA[2 * p + 1], aA2, b1);
            FFMA2(accB[2 * p],     aB2, b0);
            FFMA2(accB[2 * p + 1], aB2, b1);
        }
    }

    float fA[40], fB[40];
#pragma unroll
    for (int p = 0; p < 20; p++) {
        unpack2(accA[p], fA[2 * p], fA[2 * p + 1]);
        unpack2(accB[p], fB[2 * p], fB[2 * p + 1]);
    }

    // stores: half0 -> kk 0..12 ; half1 -> kk 13..24 + root cols (local 36..38)
    if (half == 0) {
        if (va) {
            float4* Zn = g_Z4 + (size_t)na * NKER;
#pragma unroll
            for (int g = 0; g < 13; g++)
                Zn[g] = make_float4(fA[3 * g], fA[3 * g + 1], fA[3 * g + 2], 0.f);
        }
        if (vb) {
            float4* Zn = g_Z4 + (size_t)nb * NKER;
#pragma unroll
            for (int g = 0; g < 13; g++)
                Zn[g] = make_float4(fB[3 * g], fB[3 * g + 1], fB[3 * g + 2], 0.f);
        }
    } else {
        if (va) {
            float4* Zn = g_Z4 + (size_t)na * NKER;
#pragma unroll
            for (int g = 0; g < 12; g++)
                Zn[13 + g] = make_float4(fA[3 * g], fA[3 * g + 1], fA[3 * g + 2], 0.f);
            dout[na * 3 + 0] = fA[36];
            dout[na * 3 + 1] = fA[37];
            dout[na * 3 + 2] = fA[38];
        }
        if (vb) {
            float4* Zn = g_Z4 + (size_t)nb * NKER;
#pragma unroll
            for (int g = 0; g < 12; g++)
                Zn[13 + g] = make_float4(fB[3 * g], fB[3 * g + 1], fB[3 * g + 2], 0.f);
            dout[nb * 3 + 0] = fB[36];
            dout[nb * 3 + 1] = fB[37];
            dout[nb * 3 + 2] = fB[38];
        }
    }
}

// ---------------------------------------------------------------------------
// Edge pass 2: A4[dst] += sum_s basis1_s * Z[src, idx_s, :]  (one float4 atomic)
__global__ void k_edge2(const int* __restrict__ ei, const float* __restrict__ ps,
                        int E) {
    int e = blockIdx.x * blockDim.x + threadIdx.x;
    if (e >= E) return;
    int dst = ei[e];
    int src = ei[E + e];
    float2 p = reinterpret_cast<const float2*>(ps)[e];
    float b[4]; int id[4];
    spline4(p.x, p.y, b, id);
    const float4* Z = g_Z4 + (size_t)src * NKER;
    float a0 = 0.f, a1 = 0.f, a2 = 0.f;
#pragma unroll
    for (int s = 0; s < 4; s++) {
        float4 z = __ldg(Z + id[s]);
        a0 = fmaf(b[s], z.x, a0);
        a1 = fmaf(b[s], z.y, a1);
        a2 = fmaf(b[s], z.z, a2);
    }
    atomicAdd(g_A4 + dst, make_float4(a0, a1, a2, 0.f));
}

// ---------------------------------------------------------------------------
// Final: out[n] = root_term (already in dout) + inv[n] * A4[n]
__global__ void k_final(float* __restrict__ dout, int N) {
    int n = blockIdx.x * blockDim.x + threadIdx.x;
    if (n >= N) return;
    float4 a = g_A4[n];
    float inv = g_inv[n];
    dout[n * 3 + 0] += a.x * inv;
    dout[n * 3 + 1] += a.y * inv;
    dout[n * 3 + 2] += a.z * inv;
}

// ---------------------------------------------------------------------------
extern "C" void kernel_launch(void* const* d_in, const int* in_sizes, int n_in,
                              void* d_out, int out_size) {
    const float* x   = (const float*)d_in[0];
    const int*   ei  = (const int*)d_in[1];
    const float* ps  = (const float*)d_in[2];
    const float* ps1 = (const float*)d_in[3];
    const float* w   = (const float*)d_in[4];
    const float* rw  = (const float*)d_in[5];
    const float* w1  = (const float*)d_in[6];
    const float* rw1 = (const float*)d_in[7];
    float* dout = (float*)d_out;

    int N = in_sizes[0] / 6;
    int E = in_sizes[2] / 2;
    if (N > NMAX) N = NMAX;
    if (E > EMAX) E = EMAX;

    k_zero<<<2048, 256>>>(x, N);
    int edgeBlocks = (E + 255) / 256;
    k_edge1_buildM<<<JD + edgeBlocks, 256>>>(ei, ps, E, w, rw, w1, rw1);

    size_t smemC = (size_t)(JD * SMP) * sizeof(float);   // 52416 B
    cudaFuncSetAttribute(k_zgemm, cudaFuncAttributeMaxDynamicSharedMemorySize, (int)smemC);
    k_zgemm<<<(N + 127) / 128, 128, smemC>>>(dout, N);

    k_edge2<<<(E + 255) / 256, 256>>>(ei, ps1, E);
    k_final<<<(N + 255) / 256, 256>>>(dout, N);
}